// round 7
// baseline (speedup 1.0000x reference)
#include <cuda_runtime.h>
#include <cstdint>
#include <math.h>

#define D      256
#define BROWS  4096
#define NTOT   8192
#define TILE   128
#define NB     (NTOT / TILE)          // 64 row tiles
#define NJ     (NB / 2)               // 32 column super-tiles (256 cols)
#define NST    1056                   // upper-tri super-tiles

#define QSCALE   127.0f
#define QINVSQ   (1.0f / (127.0f * 127.0f))

// ---------------------------------------------------------------------------
__device__ uint8_t g_x8[NTOT * D];    // normalized [a;b], s8 (2 MB)
__device__ float g_align[BROWS];
__device__ float g_part[NST];

// ---------------------------------------------------------------------------
__device__ __forceinline__ uint32_t smem_u32(const void* p) {
    uint32_t a;
    asm("{ .reg .u64 t; cvta.to.shared.u64 t, %1; cvt.u32.u64 %0, t; }" : "=r"(a) : "l"(p));
    return a;
}
__device__ __forceinline__ void cp_async16(uint32_t dst, const void* src) {
    asm volatile("cp.async.cg.shared.global [%0], [%1], 16;" :: "r"(dst), "l"(src));
}
#define CP_COMMIT() asm volatile("cp.async.commit_group;" ::: "memory")
#define CP_WAIT(n)  asm volatile("cp.async.wait_group %0;" :: "n"(n) : "memory")

__device__ __forceinline__ void ldmatrix_x4(uint32_t& r0, uint32_t& r1,
                                            uint32_t& r2, uint32_t& r3, uint32_t addr) {
    asm volatile("ldmatrix.sync.aligned.m8n8.x4.shared.b16 {%0,%1,%2,%3}, [%4];"
                 : "=r"(r0), "=r"(r1), "=r"(r2), "=r"(r3) : "r"(addr));
}
// s8 IMMA, K=32 per instruction, exact s32 accumulate.
__device__ __forceinline__ void mma_s8(int32_t* c, const uint32_t* a, const uint32_t* b) {
    asm volatile(
        "mma.sync.aligned.m16n8k32.row.col.s32.s8.s8.s32 "
        "{%0,%1,%2,%3}, {%4,%5,%6,%7}, {%8,%9}, {%0,%1,%2,%3};"
        : "+r"(c[0]), "+r"(c[1]), "+r"(c[2]), "+r"(c[3])
        : "r"(a[0]), "r"(a[1]), "r"(a[2]), "r"(a[3]), "r"(b[0]), "r"(b[1]));
}
// pack 4 floats (pre-scaled) -> 4 s8 bytes, byte i = element i
__device__ __forceinline__ uint32_t pack_s8(float e0, float e1, float e2, float e3) {
    int i0 = __float2int_rn(e0), i1 = __float2int_rn(e1);
    int i2 = __float2int_rn(e2), i3 = __float2int_rn(e3);
    uint32_t out;
    asm("{ .reg .b32 t;\n\t"
        "cvt.pack.sat.s8.s32.b32 t, %4, %3, 0;\n\t"
        "cvt.pack.sat.s8.s32.b32 %0, %2, %1, t;\n\t}"
        : "=r"(out) : "r"(i0), "r"(i1), "r"(i2), "r"(i3));
    return out;
}

// ---------------------------------------------------------------------------
template <int NWARP>
__device__ __forceinline__ float block_reduce(float v) {
    __shared__ float sh[NWARP];
    #pragma unroll
    for (int o = 16; o > 0; o >>= 1) v += __shfl_down_sync(0xffffffffu, v, o);
    if ((threadIdx.x & 31) == 0) sh[threadIdx.x >> 5] = v;
    __syncthreads();
    if (threadIdx.x == 0) {
        float t = 0.f;
        #pragma unroll
        for (int i = 0; i < NWARP; i++) t += sh[i];
        sh[0] = t;
    }
    __syncthreads();
    float r = sh[0];
    __syncthreads();
    return r;
}
__device__ __forceinline__ float warp_allreduce(float v) {
    #pragma unroll
    for (int o = 16; o > 0; o >>= 1) v += __shfl_xor_sync(0xffffffffu, v, o);
    return v;
}

// ---------------------------------------------------------------------------
// Kernel 1: warp-per-row L2 normalize -> s8 (scale 127), per-row align term.
__global__ __launch_bounds__(256) void normalize_kernel(
    const float* __restrict__ a, const float* __restrict__ b) {
    const int lane = threadIdx.x & 31;
    const int row  = blockIdx.x * 8 + (threadIdx.x >> 5);

    const float4* ar = (const float4*)(a + (size_t)row * D);
    const float4* br = (const float4*)(b + (size_t)row * D);
    float4 a0 = ar[lane], a1 = ar[lane + 32];
    float4 b0 = br[lane], b1 = br[lane + 32];

    float sa = warp_allreduce(a0.x*a0.x + a0.y*a0.y + a0.z*a0.z + a0.w*a0.w +
                              a1.x*a1.x + a1.y*a1.y + a1.z*a1.z + a1.w*a1.w);
    float sb = warp_allreduce(b0.x*b0.x + b0.y*b0.y + b0.z*b0.z + b0.w*b0.w +
                              b1.x*b1.x + b1.y*b1.y + b1.z*b1.z + b1.w*b1.w);

    float ra = 1.0f / fmaxf(sqrtf(sa), 1e-12f);
    float rb = 1.0f / fmaxf(sqrtf(sb), 1e-12f);

    a0.x *= ra; a0.y *= ra; a0.z *= ra; a0.w *= ra;
    a1.x *= ra; a1.y *= ra; a1.z *= ra; a1.w *= ra;
    b0.x *= rb; b0.y *= rb; b0.z *= rb; b0.w *= rb;
    b1.x *= rb; b1.y *= rb; b1.z *= rb; b1.w *= rb;

    uint32_t* xa = (uint32_t*)g_x8 + (size_t)row * 64;
    uint32_t* xb = (uint32_t*)g_x8 + (size_t)(BROWS + row) * 64;
    xa[lane]      = pack_s8(a0.x*QSCALE, a0.y*QSCALE, a0.z*QSCALE, a0.w*QSCALE);
    xa[lane + 32] = pack_s8(a1.x*QSCALE, a1.y*QSCALE, a1.z*QSCALE, a1.w*QSCALE);
    xb[lane]      = pack_s8(b0.x*QSCALE, b0.y*QSCALE, b0.z*QSCALE, b0.w*QSCALE);
    xb[lane + 32] = pack_s8(b1.x*QSCALE, b1.y*QSCALE, b1.z*QSCALE, b1.w*QSCALE);

    float dx0 = a0.x-b0.x, dy0 = a0.y-b0.y, dz0 = a0.z-b0.z, dw0 = a0.w-b0.w;
    float dx1 = a1.x-b1.x, dy1 = a1.y-b1.y, dz1 = a1.z-b1.z, dw1 = a1.w-b1.w;
    float sd = warp_allreduce(dx0*dx0 + dy0*dy0 + dz0*dz0 + dw0*dw0 +
                              dx1*dx1 + dy1*dy1 + dz1*dz1 + dw1*dw1);
    if (lane == 0) g_align[row] = sd;
}

// ---------------------------------------------------------------------------
// Kernel 2: 128x256 s8 super-tile Gram (s32 acc), double-buffered K-halves.
// Row pitch per half: 128 B (8 16B-chunks); swizzle chunk' = chunk ^ (row&7).
extern __shared__ char gsm[];
#define A_OFF(h) ((h) * 16384)
#define B_OFF(h) (32768 + (h) * 32768)
#define SMEM_TOTAL 98304

__global__ __launch_bounds__(512, 1) void gram_kernel() {
    const int tid  = threadIdx.x;
    const int wid  = tid >> 5;
    const int lane = tid & 31;
    const uint32_t smem_base = smem_u32(gsm);

    int by = 0, rem = blockIdx.x;
    while (rem >= NJ - (by >> 1)) { rem -= NJ - (by >> 1); by++; }
    const int j = (by >> 1) + rem;

    const uint8_t* __restrict__ xa = g_x8 + (size_t)(by * TILE) * D;
    const uint8_t* __restrict__ xb = g_x8 + (size_t)(j * 256) * D;

    #pragma unroll
    for (int h = 0; h < 2; h++) {
        #pragma unroll
        for (int t = 0; t < 2; t++) {          // A: 128 rows x 8 chunks
            int i = tid + t * 512;
            int r = i >> 3, c = i & 7;
            cp_async16(smem_base + A_OFF(h) + r * 128 + ((c ^ (r & 7)) << 4),
                       xa + (size_t)r * D + h * 128 + c * 16);
        }
        #pragma unroll
        for (int t = 0; t < 4; t++) {          // B: 256 rows x 8 chunks
            int i = tid + t * 512;
            int r = i >> 3, c = i & 7;
            cp_async16(smem_base + B_OFF(h) + r * 128 + ((c ^ (r & 7)) << 4),
                       xb + (size_t)r * D + h * 128 + c * 16);
        }
        CP_COMMIT();
    }

    const int warp_m = wid >> 2;
    const int warp_n = wid & 3;

    uint32_t a_row[2], a_rx[2];
    #pragma unroll
    for (int mt = 0; mt < 2; mt++) {
        int r = warp_m * 32 + mt * 16 + (lane & 15);
        a_row[mt] = (uint32_t)r * 128;
        a_rx[mt]  = r & 7;
    }
    const uint32_t a_c0 = lane >> 4;

    uint32_t b_row[4], b_rx[4];
    #pragma unroll
    for (int nt2 = 0; nt2 < 4; nt2++) {
        int r = warp_n * 64 + nt2 * 16 + (lane >> 4) * 8 + (lane & 7);
        b_row[nt2] = (uint32_t)r * 128;
        b_rx[nt2]  = r & 7;
    }
    const uint32_t b_c0 = (lane >> 3) & 1;

    int32_t acc[2][8][4];
    #pragma unroll
    for (int mt = 0; mt < 2; mt++)
        #pragma unroll
        for (int nt = 0; nt < 8; nt++)
            #pragma unroll
            for (int q = 0; q < 4; q++) acc[mt][nt][q] = 0;

    #pragma unroll
    for (int h = 0; h < 2; h++) {
        if (h == 0) { CP_WAIT(1); } else { CP_WAIT(0); }
        __syncthreads();

        const uint32_t abase = smem_base + A_OFF(h);
        const uint32_t bbase = smem_base + B_OFF(h);

        #pragma unroll
        for (int ks = 0; ks < 4; ks++) {
            uint32_t af[2][4];
            #pragma unroll
            for (int mt = 0; mt < 2; mt++)
                ldmatrix_x4(af[mt][0], af[mt][1], af[mt][2], af[mt][3],
                            abase + a_row[mt] + (((2 * ks + a_c0) ^ a_rx[mt]) << 4));
            uint32_t bf[8][2];
            #pragma unroll
            for (int nt2 = 0; nt2 < 4; nt2++) {
                uint32_t r0, r1, r2, r3;
                ldmatrix_x4(r0, r1, r2, r3,
                            bbase + b_row[nt2] + (((2 * ks + b_c0) ^ b_rx[nt2]) << 4));
                bf[nt2 * 2 + 0][0] = r0; bf[nt2 * 2 + 0][1] = r1;
                bf[nt2 * 2 + 1][0] = r2; bf[nt2 * 2 + 1][1] = r3;
            }
            #pragma unroll
            for (int mt = 0; mt < 2; mt++)
                #pragma unroll
                for (int nt = 0; nt < 8; nt++)
                    mma_s8(acc[mt][nt], af[mt], bf[nt]);
        }
        if (h == 0) __syncthreads();
    }

    // ---- Fused epilogue: c = cint/127^2; e = exp(4*min(c-1,0)); gcol > grow ----
    const int gid = lane >> 2;
    const int tig = lane & 3;
    const int grow0 = by * TILE + warp_m * 32 + gid;
    const int gcol0 = j * 256 + warp_n * 64 + tig * 2;
    float s = 0.0f;
    #pragma unroll
    for (int mt = 0; mt < 2; mt++) {
        #pragma unroll
        for (int nt = 0; nt < 8; nt++) {
            #pragma unroll
            for (int q = 0; q < 4; q++) {
                const int gr = grow0 + mt * 16 + ((q >> 1) << 3);
                const int gc = gcol0 + nt * 8 + (q & 1);
                float v = (float)acc[mt][nt][q] * QINVSQ;
                float e = __expf(4.0f * fminf(v - 1.0f, 0.0f));
                if (gc > gr) s += e;
            }
        }
    }

    s = block_reduce<16>(s);
    if (tid == 0) g_part[blockIdx.x] = s;
}

// ---------------------------------------------------------------------------
__global__ __launch_bounds__(256) void finalize_kernel(float* __restrict__ out) {
    float sa = 0.0f, su = 0.0f;
    for (int i = threadIdx.x; i < BROWS; i += 256) sa += g_align[i];
    for (int i = threadIdx.x; i < NST;   i += 256) su += g_part[i];
    sa = block_reduce<8>(sa);
    su = block_reduce<8>(su);
    if (threadIdx.x == 0) {
        double align_loss   = (double)sa / (double)BROWS;
        double uniform_loss = 2.0 * (double)su / ((double)NTOT * (double)(NTOT - 1));
        out[0] = (float)(align_loss + uniform_loss);
    }
}

// ---------------------------------------------------------------------------
extern "C" void kernel_launch(void* const* d_in, const int* in_sizes, int n_in,
                              void* d_out, int out_size) {
    const float* a = (const float*)d_in[0];
    const float* b = (const float*)d_in[1];
    float* out = (float*)d_out;

    cudaFuncSetAttribute(gram_kernel,
                         cudaFuncAttributeMaxDynamicSharedMemorySize, SMEM_TOTAL);

    normalize_kernel<<<BROWS / 8, 256>>>(a, b);
    gram_kernel<<<NST, 512, SMEM_TOTAL>>>();
    finalize_kernel<<<1, 256>>>(out);
}

// round 8
// speedup vs baseline: 1.5758x; 1.5758x over previous
#include <cuda_runtime.h>
#include <cuda_fp16.h>
#include <cstdint>
#include <math.h>

#define D      256
#define BROWS  4096
#define NTOT   8192
#define TILE   128
#define NB     (NTOT / TILE)            // 64 row/col tiles
#define NTILES (NB * (NB + 1) / 2)      // 2080 upper-tri tiles
#define NCTA   148                      // persistent CTAs (1/SM)

// ---------------------------------------------------------------------------
__device__ uint8_t g_x8[NTOT * D];      // normalized [a;b], e4m3 (2 MB)
__device__ float g_align[BROWS];
__device__ float g_part[NTILES];
__device__ unsigned int g_ticket;
__device__ unsigned int g_done;

// ---------------------------------------------------------------------------
__device__ __forceinline__ uint32_t smem_u32(const void* p) {
    uint32_t a;
    asm("{ .reg .u64 t; cvta.to.shared.u64 t, %1; cvt.u32.u64 %0, t; }" : "=r"(a) : "l"(p));
    return a;
}
__device__ __forceinline__ void cp_async16(uint32_t dst, const void* src) {
    asm volatile("cp.async.cg.shared.global [%0], [%1], 16;" :: "r"(dst), "l"(src));
}
#define CP_COMMIT() asm volatile("cp.async.commit_group;" ::: "memory")
#define CP_WAIT(n)  asm volatile("cp.async.wait_group %0;" :: "n"(n) : "memory")

__device__ __forceinline__ void ldmatrix_x4(uint32_t& r0, uint32_t& r1,
                                            uint32_t& r2, uint32_t& r3, uint32_t addr) {
    asm volatile("ldmatrix.sync.aligned.m8n8.x4.shared.b16 {%0,%1,%2,%3}, [%4];"
                 : "=r"(r0), "=r"(r1), "=r"(r2), "=r"(r3) : "r"(addr));
}
// fp8 e4m3 MMA, K=32, fp16 accumulator (fastest legacy-path variant measured).
__device__ __forceinline__ void mma_fp8_h(uint32_t* c, const uint32_t* a, const uint32_t* b) {
    asm volatile(
        "mma.sync.aligned.m16n8k32.row.col.f16.e4m3.e4m3.f16 "
        "{%0,%1}, {%2,%3,%4,%5}, {%6,%7}, {%0,%1};"
        : "+r"(c[0]), "+r"(c[1])
        : "r"(a[0]), "r"(a[1]), "r"(a[2]), "r"(a[3]), "r"(b[0]), "r"(b[1]));
}
__device__ __forceinline__ uint32_t pack_e4m3(float e0, float e1, float e2, float e3) {
    uint32_t out;
    asm("{ .reg .b16 lo, hi;\n\t"
        "cvt.rn.satfinite.e4m3x2.f32 lo, %2, %1;\n\t"
        "cvt.rn.satfinite.e4m3x2.f32 hi, %4, %3;\n\t"
        "mov.b32 %0, {lo, hi}; }"
        : "=r"(out) : "f"(e0), "f"(e1), "f"(e2), "f"(e3));
    return out;
}

// ---------------------------------------------------------------------------
template <int NWARP>
__device__ __forceinline__ float block_reduce(float v) {
    __shared__ float sh[NWARP];
    #pragma unroll
    for (int o = 16; o > 0; o >>= 1) v += __shfl_down_sync(0xffffffffu, v, o);
    if ((threadIdx.x & 31) == 0) sh[threadIdx.x >> 5] = v;
    __syncthreads();
    if (threadIdx.x == 0) {
        float t = 0.f;
        #pragma unroll
        for (int i = 0; i < NWARP; i++) t += sh[i];
        sh[0] = t;
    }
    __syncthreads();
    float r = sh[0];
    __syncthreads();
    return r;
}
__device__ __forceinline__ float warp_allreduce(float v) {
    #pragma unroll
    for (int o = 16; o > 0; o >>= 1) v += __shfl_xor_sync(0xffffffffu, v, o);
    return v;
}

// ---------------------------------------------------------------------------
// Kernel 1: warp-per-row L2 normalize -> e4m3, per-row align term.
// Also resets the gram kernel's ticket/arrival counters (per launch).
__global__ __launch_bounds__(128) void normalize_kernel(
    const float* __restrict__ a, const float* __restrict__ b) {
    if (blockIdx.x == 0 && threadIdx.x == 0) { g_ticket = 0u; g_done = 0u; }

    const int lane = threadIdx.x & 31;
    const int row  = blockIdx.x * 4 + (threadIdx.x >> 5);

    const float4* ar = (const float4*)(a + (size_t)row * D);
    const float4* br = (const float4*)(b + (size_t)row * D);
    float4 a0 = ar[lane], a1 = ar[lane + 32];
    float4 b0 = br[lane], b1 = br[lane + 32];

    float sa = warp_allreduce(a0.x*a0.x + a0.y*a0.y + a0.z*a0.z + a0.w*a0.w +
                              a1.x*a1.x + a1.y*a1.y + a1.z*a1.z + a1.w*a1.w);
    float sb = warp_allreduce(b0.x*b0.x + b0.y*b0.y + b0.z*b0.z + b0.w*b0.w +
                              b1.x*b1.x + b1.y*b1.y + b1.z*b1.z + b1.w*b1.w);

    float ra = 1.0f / fmaxf(sqrtf(sa), 1e-12f);
    float rb = 1.0f / fmaxf(sqrtf(sb), 1e-12f);

    a0.x *= ra; a0.y *= ra; a0.z *= ra; a0.w *= ra;
    a1.x *= ra; a1.y *= ra; a1.z *= ra; a1.w *= ra;
    b0.x *= rb; b0.y *= rb; b0.z *= rb; b0.w *= rb;
    b1.x *= rb; b1.y *= rb; b1.z *= rb; b1.w *= rb;

    uint32_t* xa = (uint32_t*)g_x8 + (size_t)row * 64;
    uint32_t* xb = (uint32_t*)g_x8 + (size_t)(BROWS + row) * 64;
    xa[lane]      = pack_e4m3(a0.x, a0.y, a0.z, a0.w);
    xa[lane + 32] = pack_e4m3(a1.x, a1.y, a1.z, a1.w);
    xb[lane]      = pack_e4m3(b0.x, b0.y, b0.z, b0.w);
    xb[lane + 32] = pack_e4m3(b1.x, b1.y, b1.z, b1.w);

    float dx0 = a0.x-b0.x, dy0 = a0.y-b0.y, dz0 = a0.z-b0.z, dw0 = a0.w-b0.w;
    float dx1 = a1.x-b1.x, dy1 = a1.y-b1.y, dz1 = a1.z-b1.z, dw1 = a1.w-b1.w;
    float sd = warp_allreduce(dx0*dx0 + dy0*dy0 + dz0*dz0 + dw0*dw0 +
                              dx1*dx1 + dy1*dy1 + dz1*dz1 + dw1*dw1);
    if (lane == 0) g_align[row] = sd;
}

// ---------------------------------------------------------------------------
// Kernel 2: persistent fp8 Gram. 148 CTAs, dynamic 128x128 tiles via ticket,
// cross-tile double-buffered cp.async, fused exp epilogue, fused final reduce.
// Smem buffer b: A @ b*65536, B @ b*65536+32768. Row pitch 256 B (16 chunks),
// swizzle chunk' = chunk ^ (row&7).
extern __shared__ char gsm[];
#define BUF_A(b) ((b) * 65536)
#define BUF_B(b) ((b) * 65536 + 32768)
#define SMEM_TOTAL 131072

__device__ __forceinline__ void tile_decode(int t, int& by, int& bx) {
    int y = 0, rem = t;
    while (rem >= NB - y) { rem -= NB - y; y++; }
    by = y; bx = y + rem;
}

__device__ __forceinline__ void prefetch_tile(int t, uint32_t smem_base, int buf, int tid) {
    int by, bx; tile_decode(t, by, bx);
    const uint8_t* __restrict__ xa = g_x8 + (size_t)(by * TILE) * D;
    #pragma unroll
    for (int e = 0; e < 4; e++) {               // A: 128 rows x 16 chunks
        int i = tid + e * 512;
        int r = i >> 4, c = i & 15;
        cp_async16(smem_base + BUF_A(buf) + r * 256 + ((c ^ (r & 7)) << 4),
                   xa + (size_t)r * D + c * 16);
    }
    if (bx != by) {
        const uint8_t* __restrict__ xb = g_x8 + (size_t)(bx * TILE) * D;
        #pragma unroll
        for (int e = 0; e < 4; e++) {           // B: 128 rows x 16 chunks
            int i = tid + e * 512;
            int r = i >> 4, c = i & 15;
            cp_async16(smem_base + BUF_B(buf) + r * 256 + ((c ^ (r & 7)) << 4),
                       xb + (size_t)r * D + c * 16);
        }
    }
    CP_COMMIT();
}

__global__ __launch_bounds__(512, 1) void gram_kernel(float* __restrict__ out) {
    const int tid  = threadIdx.x;
    const int wid  = tid >> 5;
    const int lane = tid & 31;
    const uint32_t smem_base = smem_u32(gsm);

    __shared__ int s_next;
    __shared__ unsigned s_rank;

    // Warp tiling: 4 (m) x 4 (n); warp tile 32 x 32.
    const int warp_m = wid >> 2;
    const int warp_n = wid & 3;

    // Fragment address components (row-dependent, buffer-independent).
    uint32_t a_row[2], a_rx[2];
    #pragma unroll
    for (int mt = 0; mt < 2; mt++) {
        int r = warp_m * 32 + mt * 16 + (lane & 15);
        a_row[mt] = (uint32_t)r * 256;
        a_rx[mt]  = r & 7;
    }
    const uint32_t a_c0 = lane >> 4;
    uint32_t b_row[2], b_rx[2];
    #pragma unroll
    for (int nt2 = 0; nt2 < 2; nt2++) {
        int r = warp_n * 32 + nt2 * 16 + (lane >> 4) * 8 + (lane & 7);
        b_row[nt2] = (uint32_t)r * 256;
        b_rx[nt2]  = r & 7;
    }
    const uint32_t b_c0 = (lane >> 3) & 1;

    // First ticket + prefetch.
    if (tid == 0) s_next = (int)atomicAdd(&g_ticket, 1u);
    __syncthreads();
    int cur = s_next;
    int pbuf = 0;
    if (cur < NTILES) prefetch_tile(cur, smem_base, 0, tid);

    while (cur < NTILES) {
        if (tid == 0) s_next = (int)atomicAdd(&g_ticket, 1u);
        __syncthreads();
        const int nxt = s_next;
        if (nxt < NTILES) {
            prefetch_tile(nxt, smem_base, pbuf ^ 1, tid);
            CP_WAIT(1);
        } else {
            CP_WAIT(0);
        }
        __syncthreads();

        int by, bx; tile_decode(cur, by, bx);
        const bool diag = (bx == by);
        const uint32_t abase = smem_base + BUF_A(pbuf);
        const uint32_t bbase = diag ? abase : (smem_base + BUF_B(pbuf));

        uint32_t acc[2][4][2];
        #pragma unroll
        for (int mt = 0; mt < 2; mt++)
            #pragma unroll
            for (int nt = 0; nt < 4; nt++) { acc[mt][nt][0] = 0u; acc[mt][nt][1] = 0u; }

        #pragma unroll
        for (int ks = 0; ks < 8; ks++) {
            uint32_t af[2][4];
            #pragma unroll
            for (int mt = 0; mt < 2; mt++)
                ldmatrix_x4(af[mt][0], af[mt][1], af[mt][2], af[mt][3],
                            abase + a_row[mt] + (((2 * ks + a_c0) ^ a_rx[mt]) << 4));
            uint32_t bf[4][2];
            #pragma unroll
            for (int nt2 = 0; nt2 < 2; nt2++) {
                uint32_t r0, r1, r2, r3;
                ldmatrix_x4(r0, r1, r2, r3,
                            bbase + b_row[nt2] + (((2 * ks + b_c0) ^ b_rx[nt2]) << 4));
                bf[nt2 * 2 + 0][0] = r0; bf[nt2 * 2 + 0][1] = r1;
                bf[nt2 * 2 + 1][0] = r2; bf[nt2 * 2 + 1][1] = r3;
            }
            #pragma unroll
            for (int mt = 0; mt < 2; mt++)
                #pragma unroll
                for (int nt = 0; nt < 4; nt++)
                    mma_fp8_h(acc[mt][nt], af[mt], bf[nt]);
        }

        // Epilogue: e = exp(4*min(c-1,0)); include iff gcol > grow.
        const int gid = lane >> 2;
        const int tig = lane & 3;
        const int grow0 = by * TILE + warp_m * 32 + gid;
        const int gcol0 = bx * TILE + warp_n * 32 + tig * 2;
        float s = 0.0f;
        #pragma unroll
        for (int mt = 0; mt < 2; mt++) {
            #pragma unroll
            for (int nt = 0; nt < 4; nt++) {
                float2 f0 = __half22float2(*(const __half2*)&acc[mt][nt][0]);
                float2 f1 = __half22float2(*(const __half2*)&acc[mt][nt][1]);
                const int gr = grow0 + mt * 16;
                const int gc = gcol0 + nt * 8;
                float e;
                e = __expf(4.0f * fminf(f0.x - 1.0f, 0.0f)); if (gc     > gr    ) s += e;
                e = __expf(4.0f * fminf(f0.y - 1.0f, 0.0f)); if (gc + 1 > gr    ) s += e;
                e = __expf(4.0f * fminf(f1.x - 1.0f, 0.0f)); if (gc     > gr + 8) s += e;
                e = __expf(4.0f * fminf(f1.y - 1.0f, 0.0f)); if (gc + 1 > gr + 8) s += e;
            }
        }
        s = block_reduce<16>(s);
        if (tid == 0) g_part[cur] = s;

        cur = nxt;
        pbuf ^= 1;
    }

    // Fused final reduction: last-arriving CTA sums everything (fixed order).
    __threadfence();
    if (tid == 0) s_rank = atomicAdd(&g_done, 1u);
    __syncthreads();
    if (s_rank == NCTA - 1) {
        float sa = 0.0f, su = 0.0f;
        for (int i = tid; i < BROWS;  i += 512) sa += g_align[i];
        for (int i = tid; i < NTILES; i += 512) su += g_part[i];
        sa = block_reduce<16>(sa);
        su = block_reduce<16>(su);
        if (tid == 0) {
            double align_loss   = (double)sa / (double)BROWS;
            double uniform_loss = 2.0 * (double)su / ((double)NTOT * (double)(NTOT - 1));
            out[0] = (float)(align_loss + uniform_loss);
        }
    }
}

// ---------------------------------------------------------------------------
extern "C" void kernel_launch(void* const* d_in, const int* in_sizes, int n_in,
                              void* d_out, int out_size) {
    const float* a = (const float*)d_in[0];
    const float* b = (const float*)d_in[1];
    float* out = (float*)d_out;

    cudaFuncSetAttribute(gram_kernel,
                         cudaFuncAttributeMaxDynamicSharedMemorySize, SMEM_TOTAL);

    normalize_kernel<<<BROWS / 4, 128>>>(a, b);
    gram_kernel<<<NCTA, 512, SMEM_TOTAL>>>(out);
}

// round 9
// speedup vs baseline: 1.7586x; 1.1160x over previous
#include <cuda_runtime.h>
#include <cuda_fp16.h>
#include <cstdint>
#include <math.h>

#define D      256
#define BROWS  4096
#define NTOT   8192
#define TILE   128
#define NB     (NTOT / TILE)            // 64 row tiles
#define NJ     (NB / 2)                 // 32 column super-tiles (256 cols)
#define NST    1056                     // upper-tri super-tiles
#define NCTA   148                      // persistent CTAs (1/SM)

// ---------------------------------------------------------------------------
__device__ uint8_t g_x8[NTOT * D];      // normalized [a;b], e4m3 (2 MB)
__device__ float g_align[BROWS];
__device__ float g_part[NST];
__device__ unsigned int g_ticket;
__device__ unsigned int g_done;

// ---------------------------------------------------------------------------
__device__ __forceinline__ uint32_t smem_u32(const void* p) {
    uint32_t a;
    asm("{ .reg .u64 t; cvta.to.shared.u64 t, %1; cvt.u32.u64 %0, t; }" : "=r"(a) : "l"(p));
    return a;
}
__device__ __forceinline__ void cp_async16(uint32_t dst, const void* src) {
    asm volatile("cp.async.cg.shared.global [%0], [%1], 16;" :: "r"(dst), "l"(src));
}
#define CP_COMMIT() asm volatile("cp.async.commit_group;" ::: "memory")
#define CP_WAIT(n)  asm volatile("cp.async.wait_group %0;" :: "n"(n) : "memory")

__device__ __forceinline__ void ldmatrix_x4(uint32_t& r0, uint32_t& r1,
                                            uint32_t& r2, uint32_t& r3, uint32_t addr) {
    asm volatile("ldmatrix.sync.aligned.m8n8.x4.shared.b16 {%0,%1,%2,%3}, [%4];"
                 : "=r"(r0), "=r"(r1), "=r"(r2), "=r"(r3) : "r"(addr));
}
// fp8 e4m3 MMA, K=32, fp16 accumulator (fastest measured legacy-path variant).
__device__ __forceinline__ void mma_fp8_h(uint32_t* c, const uint32_t* a, const uint32_t* b) {
    asm volatile(
        "mma.sync.aligned.m16n8k32.row.col.f16.e4m3.e4m3.f16 "
        "{%0,%1}, {%2,%3,%4,%5}, {%6,%7}, {%0,%1};"
        : "+r"(c[0]), "+r"(c[1])
        : "r"(a[0]), "r"(a[1]), "r"(a[2]), "r"(a[3]), "r"(b[0]), "r"(b[1]));
}
__device__ __forceinline__ uint32_t pack_e4m3(float e0, float e1, float e2, float e3) {
    uint32_t out;
    asm("{ .reg .b16 lo, hi;\n\t"
        "cvt.rn.satfinite.e4m3x2.f32 lo, %2, %1;\n\t"
        "cvt.rn.satfinite.e4m3x2.f32 hi, %4, %3;\n\t"
        "mov.b32 %0, {lo, hi}; }"
        : "=r"(out) : "f"(e0), "f"(e1), "f"(e2), "f"(e3));
    return out;
}

// ---------------------------------------------------------------------------
template <int NWARP>
__device__ __forceinline__ float block_reduce(float v) {
    __shared__ float sh[NWARP];
    #pragma unroll
    for (int o = 16; o > 0; o >>= 1) v += __shfl_down_sync(0xffffffffu, v, o);
    if ((threadIdx.x & 31) == 0) sh[threadIdx.x >> 5] = v;
    __syncthreads();
    if (threadIdx.x == 0) {
        float t = 0.f;
        #pragma unroll
        for (int i = 0; i < NWARP; i++) t += sh[i];
        sh[0] = t;
    }
    __syncthreads();
    float r = sh[0];
    __syncthreads();
    return r;
}
__device__ __forceinline__ float warp_allreduce(float v) {
    #pragma unroll
    for (int o = 16; o > 0; o >>= 1) v += __shfl_xor_sync(0xffffffffu, v, o);
    return v;
}

// ---------------------------------------------------------------------------
// Kernel 1: warp-per-row L2 normalize -> e4m3; also resets counters.
__global__ __launch_bounds__(256) void normalize_kernel(
    const float* __restrict__ a, const float* __restrict__ b) {
    if (blockIdx.x == 0 && threadIdx.x == 0) { g_ticket = 0u; g_done = 0u; }

    const int lane = threadIdx.x & 31;
    const int row  = blockIdx.x * 8 + (threadIdx.x >> 5);

    const float4* ar = (const float4*)(a + (size_t)row * D);
    const float4* br = (const float4*)(b + (size_t)row * D);
    float4 a0 = ar[lane], a1 = ar[lane + 32];
    float4 b0 = br[lane], b1 = br[lane + 32];

    float sa = warp_allreduce(a0.x*a0.x + a0.y*a0.y + a0.z*a0.z + a0.w*a0.w +
                              a1.x*a1.x + a1.y*a1.y + a1.z*a1.z + a1.w*a1.w);
    float sb = warp_allreduce(b0.x*b0.x + b0.y*b0.y + b0.z*b0.z + b0.w*b0.w +
                              b1.x*b1.x + b1.y*b1.y + b1.z*b1.z + b1.w*b1.w);

    float ra = 1.0f / fmaxf(sqrtf(sa), 1e-12f);
    float rb = 1.0f / fmaxf(sqrtf(sb), 1e-12f);

    a0.x *= ra; a0.y *= ra; a0.z *= ra; a0.w *= ra;
    a1.x *= ra; a1.y *= ra; a1.z *= ra; a1.w *= ra;
    b0.x *= rb; b0.y *= rb; b0.z *= rb; b0.w *= rb;
    b1.x *= rb; b1.y *= rb; b1.z *= rb; b1.w *= rb;

    uint32_t* xa = (uint32_t*)g_x8 + (size_t)row * 64;
    uint32_t* xb = (uint32_t*)g_x8 + (size_t)(BROWS + row) * 64;
    xa[lane]      = pack_e4m3(a0.x, a0.y, a0.z, a0.w);
    xa[lane + 32] = pack_e4m3(a1.x, a1.y, a1.z, a1.w);
    xb[lane]      = pack_e4m3(b0.x, b0.y, b0.z, b0.w);
    xb[lane + 32] = pack_e4m3(b1.x, b1.y, b1.z, b1.w);

    float dx0 = a0.x-b0.x, dy0 = a0.y-b0.y, dz0 = a0.z-b0.z, dw0 = a0.w-b0.w;
    float dx1 = a1.x-b1.x, dy1 = a1.y-b1.y, dz1 = a1.z-b1.z, dw1 = a1.w-b1.w;
    float sd = warp_allreduce(dx0*dx0 + dy0*dy0 + dz0*dz0 + dw0*dw0 +
                              dx1*dx1 + dy1*dy1 + dz1*dz1 + dw1*dw1);
    if (lane == 0) g_align[row] = sd;
}

// ---------------------------------------------------------------------------
// Kernel 2: persistent fp8 Gram, 128x256 super-tiles, double-buffered.
// Buffer b (96 KB): A @ b*98304 (32 KB), B @ b*98304+32768 (64 KB).
// Row pitch 256 B (16 chunks); swizzle chunk' = chunk ^ (row&7).
extern __shared__ char gsm[];
#define BUF_A(b) ((b) * 98304)
#define BUF_B(b) ((b) * 98304 + 32768)
#define SMEM_TOTAL 196608

__device__ __forceinline__ void st_decode(int t, int& by, int& j) {
    int y = 0, rem = t;
    while (rem >= NJ - (y >> 1)) { rem -= NJ - (y >> 1); y++; }
    by = y; j = (y >> 1) + rem;
}

__device__ __forceinline__ void prefetch_st(int t, uint32_t smem_base, int buf, int tid) {
    int by, j; st_decode(t, by, j);
    const uint8_t* __restrict__ xa = g_x8 + (size_t)(by * TILE) * D;
    const uint8_t* __restrict__ xb = g_x8 + (size_t)(j * 256) * D;
    #pragma unroll
    for (int e = 0; e < 4; e++) {               // A: 128 rows x 16 chunks
        int i = tid + e * 512;
        int r = i >> 4, c = i & 15;
        cp_async16(smem_base + BUF_A(buf) + r * 256 + ((c ^ (r & 7)) << 4),
                   xa + (size_t)r * D + c * 16);
    }
    #pragma unroll
    for (int e = 0; e < 8; e++) {               // B: 256 rows x 16 chunks
        int i = tid + e * 512;
        int r = i >> 4, c = i & 15;
        cp_async16(smem_base + BUF_B(buf) + r * 256 + ((c ^ (r & 7)) << 4),
                   xb + (size_t)r * D + c * 16);
    }
    CP_COMMIT();
}

__global__ __launch_bounds__(512, 1) void gram_kernel(float* __restrict__ out) {
    const int tid  = threadIdx.x;
    const int wid  = tid >> 5;
    const int lane = tid & 31;
    const uint32_t smem_base = smem_u32(gsm);

    __shared__ int s_next;
    __shared__ unsigned s_rank;

    // Warp tiling: 4 (m) x 4 (n); warp tile 32 x 64 (16 acc chains).
    const int warp_m = wid >> 2;
    const int warp_n = wid & 3;

    uint32_t a_row[2], a_rx[2];
    #pragma unroll
    for (int mt = 0; mt < 2; mt++) {
        int r = warp_m * 32 + mt * 16 + (lane & 15);
        a_row[mt] = (uint32_t)r * 256;
        a_rx[mt]  = r & 7;
    }
    const uint32_t a_c0 = lane >> 4;
    uint32_t b_row[4], b_rx[4];
    #pragma unroll
    for (int nt2 = 0; nt2 < 4; nt2++) {
        int r = warp_n * 64 + nt2 * 16 + (lane >> 4) * 8 + (lane & 7);
        b_row[nt2] = (uint32_t)r * 256;
        b_rx[nt2]  = r & 7;
    }
    const uint32_t b_c0 = (lane >> 3) & 1;

    if (tid == 0) s_next = (int)atomicAdd(&g_ticket, 1u);
    __syncthreads();
    int cur = s_next;
    int pbuf = 0;
    if (cur < NST) prefetch_st(cur, smem_base, 0, tid);

    while (cur < NST) {
        if (tid == 0) s_next = (int)atomicAdd(&g_ticket, 1u);
        __syncthreads();
        const int nxt = s_next;
        if (nxt < NST) {
            prefetch_st(nxt, smem_base, pbuf ^ 1, tid);
            CP_WAIT(1);
        } else {
            CP_WAIT(0);
        }
        __syncthreads();

        int by, j; st_decode(cur, by, j);
        const uint32_t abase = smem_base + BUF_A(pbuf);
        const uint32_t bbase = smem_base + BUF_B(pbuf);

        uint32_t acc[2][8][2];
        #pragma unroll
        for (int mt = 0; mt < 2; mt++)
            #pragma unroll
            for (int nt = 0; nt < 8; nt++) { acc[mt][nt][0] = 0u; acc[mt][nt][1] = 0u; }

        #pragma unroll
        for (int ks = 0; ks < 8; ks++) {
            uint32_t af[2][4];
            #pragma unroll
            for (int mt = 0; mt < 2; mt++)
                ldmatrix_x4(af[mt][0], af[mt][1], af[mt][2], af[mt][3],
                            abase + a_row[mt] + (((2 * ks + a_c0) ^ a_rx[mt]) << 4));
            uint32_t bf[8][2];
            #pragma unroll
            for (int nt2 = 0; nt2 < 4; nt2++) {
                uint32_t r0, r1, r2, r3;
                ldmatrix_x4(r0, r1, r2, r3,
                            bbase + b_row[nt2] + (((2 * ks + b_c0) ^ b_rx[nt2]) << 4));
                bf[nt2 * 2 + 0][0] = r0; bf[nt2 * 2 + 0][1] = r1;
                bf[nt2 * 2 + 1][0] = r2; bf[nt2 * 2 + 1][1] = r3;
            }
            #pragma unroll
            for (int mt = 0; mt < 2; mt++)
                #pragma unroll
                for (int nt = 0; nt < 8; nt++)
                    mma_fp8_h(acc[mt][nt], af[mt], bf[nt]);
        }

        // Epilogue: e = exp(4*min(c-1,0)); include iff gcol > grow.
        const int gid = lane >> 2;
        const int tig = lane & 3;
        const int grow0 = by * TILE + warp_m * 32 + gid;
        const int gcol0 = j * 256 + warp_n * 64 + tig * 2;
        float s = 0.0f;
        #pragma unroll
        for (int mt = 0; mt < 2; mt++) {
            #pragma unroll
            for (int nt = 0; nt < 8; nt++) {
                float2 f0 = __half22float2(*(const __half2*)&acc[mt][nt][0]);
                float2 f1 = __half22float2(*(const __half2*)&acc[mt][nt][1]);
                const int gr = grow0 + mt * 16;
                const int gc = gcol0 + nt * 8;
                float e;
                e = __expf(4.0f * fminf(f0.x - 1.0f, 0.0f)); if (gc     > gr    ) s += e;
                e = __expf(4.0f * fminf(f0.y - 1.0f, 0.0f)); if (gc + 1 > gr    ) s += e;
                e = __expf(4.0f * fminf(f1.x - 1.0f, 0.0f)); if (gc     > gr + 8) s += e;
                e = __expf(4.0f * fminf(f1.y - 1.0f, 0.0f)); if (gc + 1 > gr + 8) s += e;
            }
        }
        s = block_reduce<16>(s);
        if (tid == 0) g_part[cur] = s;

        cur = nxt;
        pbuf ^= 1;
    }

    // Fused final reduction in the last-arriving CTA (fixed index order).
    __threadfence();
    if (tid == 0) s_rank = atomicAdd(&g_done, 1u);
    __syncthreads();
    if (s_rank == NCTA - 1) {
        float sa = 0.0f, su = 0.0f;
        for (int i = tid; i < BROWS; i += 512) sa += g_align[i];
        for (int i = tid; i < NST;   i += 512) su += g_part[i];
        sa = block_reduce<16>(sa);
        su = block_reduce<16>(su);
        if (tid == 0) {
            double align_loss   = (double)sa / (double)BROWS;
            double uniform_loss = 2.0 * (double)su / ((double)NTOT * (double)(NTOT - 1));
            out[0] = (float)(align_loss + uniform_loss);
        }
    }
}

// ---------------------------------------------------------------------------
extern "C" void kernel_launch(void* const* d_in, const int* in_sizes, int n_in,
                              void* d_out, int out_size) {
    const float* a = (const float*)d_in[0];
    const float* b = (const float*)d_in[1];
    float* out = (float*)d_out;

    cudaFuncSetAttribute(gram_kernel,
                         cudaFuncAttributeMaxDynamicSharedMemorySize, SMEM_TOTAL);

    normalize_kernel<<<BROWS / 8, 256>>>(a, b);
    gram_kernel<<<NCTA, 512, SMEM_TOTAL>>>(out);
}

// round 11
// speedup vs baseline: 1.7996x; 1.0233x over previous
#include <cuda_runtime.h>
#include <cuda_fp16.h>
#include <cstdint>
#include <math.h>

#define D      256
#define BROWS  4096
#define NTOT   8192
#define TILE   128
#define NB     (NTOT / TILE)            // 64 row tiles
#define NJ     (NB / 2)                 // 32 column super-tiles
#define NST    1056                     // upper-tri super-tiles

// ---------------------------------------------------------------------------
__device__ uint8_t g_x8[NTOT * D];      // normalized [a;b], e4m3 (2 MB)
__device__ float g_align[BROWS];
__device__ float g_part[NST];
__device__ unsigned int g_done;

// ---------------------------------------------------------------------------
__device__ __forceinline__ uint32_t smem_u32(const void* p) {
    uint32_t a;
    asm("{ .reg .u64 t; cvta.to.shared.u64 t, %1; cvt.u32.u64 %0, t; }" : "=r"(a) : "l"(p));
    return a;
}
__device__ __forceinline__ void cp_async16(uint32_t dst, const void* src) {
    asm volatile("cp.async.cg.shared.global [%0], [%1], 16;" :: "r"(dst), "l"(src));
}
#define CP_COMMIT() asm volatile("cp.async.commit_group;" ::: "memory")
#define CP_WAIT(n)  asm volatile("cp.async.wait_group %0;" :: "n"(n) : "memory")

__device__ __forceinline__ void ldmatrix_x4(uint32_t& r0, uint32_t& r1,
                                            uint32_t& r2, uint32_t& r3, uint32_t addr) {
    asm volatile("ldmatrix.sync.aligned.m8n8.x4.shared.b16 {%0,%1,%2,%3}, [%4];"
                 : "=r"(r0), "=r"(r1), "=r"(r2), "=r"(r3) : "r"(addr));
}
// fp8 e4m3 MMA, K=32, fp16 accumulator (fastest measured legacy-path variant).
__device__ __forceinline__ void mma_fp8_h(uint32_t* c, const uint32_t* a, const uint32_t* b) {
    asm volatile(
        "mma.sync.aligned.m16n8k32.row.col.f16.e4m3.e4m3.f16 "
        "{%0,%1}, {%2,%3,%4,%5}, {%6,%7}, {%0,%1};"
        : "+r"(c[0]), "+r"(c[1])
        : "r"(a[0]), "r"(a[1]), "r"(a[2]), "r"(a[3]), "r"(b[0]), "r"(b[1]));
}
__device__ __forceinline__ uint32_t pack_e4m3(float e0, float e1, float e2, float e3) {
    uint32_t out;
    asm("{ .reg .b16 lo, hi;\n\t"
        "cvt.rn.satfinite.e4m3x2.f32 lo, %2, %1;\n\t"
        "cvt.rn.satfinite.e4m3x2.f32 hi, %4, %3;\n\t"
        "mov.b32 %0, {lo, hi}; }"
        : "=r"(out) : "f"(e0), "f"(e1), "f"(e2), "f"(e3));
    return out;
}

// ---------------------------------------------------------------------------
template <int NWARP>
__device__ __forceinline__ float block_reduce(float v) {
    __shared__ float sh[NWARP];
    #pragma unroll
    for (int o = 16; o > 0; o >>= 1) v += __shfl_down_sync(0xffffffffu, v, o);
    if ((threadIdx.x & 31) == 0) sh[threadIdx.x >> 5] = v;
    __syncthreads();
    if (threadIdx.x == 0) {
        float t = 0.f;
        #pragma unroll
        for (int i = 0; i < NWARP; i++) t += sh[i];
        sh[0] = t;
    }
    __syncthreads();
    float r = sh[0];
    __syncthreads();
    return r;
}
__device__ __forceinline__ float warp_allreduce(float v) {
    #pragma unroll
    for (int o = 16; o > 0; o >>= 1) v += __shfl_xor_sync(0xffffffffu, v, o);
    return v;
}

// ---------------------------------------------------------------------------
// Kernel 1: warp-per-row L2 normalize -> e4m3; resets g_done.
__global__ __launch_bounds__(256) void normalize_kernel(
    const float* __restrict__ a, const float* __restrict__ b) {
    if (blockIdx.x == 0 && threadIdx.x == 0) g_done = 0u;

    const int lane = threadIdx.x & 31;
    const int row  = blockIdx.x * 8 + (threadIdx.x >> 5);

    const float4* ar = (const float4*)(a + (size_t)row * D);
    const float4* br = (const float4*)(b + (size_t)row * D);
    float4 a0 = ar[lane], a1 = ar[lane + 32];
    float4 b0 = br[lane], b1 = br[lane + 32];

    float sa = warp_allreduce(a0.x*a0.x + a0.y*a0.y + a0.z*a0.z + a0.w*a0.w +
                              a1.x*a1.x + a1.y*a1.y + a1.z*a1.z + a1.w*a1.w);
    float sb = warp_allreduce(b0.x*b0.x + b0.y*b0.y + b0.z*b0.z + b0.w*b0.w +
                              b1.x*b1.x + b1.y*b1.y + b1.z*b1.z + b1.w*b1.w);

    float ra = 1.0f / fmaxf(sqrtf(sa), 1e-12f);
    float rb = 1.0f / fmaxf(sqrtf(sb), 1e-12f);

    a0.x *= ra; a0.y *= ra; a0.z *= ra; a0.w *= ra;
    a1.x *= ra; a1.y *= ra; a1.z *= ra; a1.w *= ra;
    b0.x *= rb; b0.y *= rb; b0.z *= rb; b0.w *= rb;
    b1.x *= rb; b1.y *= rb; b1.z *= rb; b1.w *= rb;

    uint32_t* xa = (uint32_t*)g_x8 + (size_t)row * 64;
    uint32_t* xb = (uint32_t*)g_x8 + (size_t)(BROWS + row) * 64;
    xa[lane]      = pack_e4m3(a0.x, a0.y, a0.z, a0.w);
    xa[lane + 32] = pack_e4m3(a1.x, a1.y, a1.z, a1.w);
    xb[lane]      = pack_e4m3(b0.x, b0.y, b0.z, b0.w);
    xb[lane + 32] = pack_e4m3(b1.x, b1.y, b1.z, b1.w);

    float dx0 = a0.x-b0.x, dy0 = a0.y-b0.y, dz0 = a0.z-b0.z, dw0 = a0.w-b0.w;
    float dx1 = a1.x-b1.x, dy1 = a1.y-b1.y, dz1 = a1.z-b1.z, dw1 = a1.w-b1.w;
    float sd = warp_allreduce(dx0*dx0 + dy0*dy0 + dz0*dz0 + dw0*dw0 +
                              dx1*dx1 + dy1*dy1 + dz1*dz1 + dw1*dw1);
    if (lane == 0) g_align[row] = sd;
}

// ---------------------------------------------------------------------------
// Kernel 2: 128x256 fp8 super-tile Gram, K-half double-buffered cp.async,
// software-pipelined fragments (base-safe XOR offsets), fused exp epilogue,
// fused final reduce. Smem per half: A @ h*16384, B @ 32768 + h*32768.
// Row pitch 128 B (8 chunks); swizzle chunk' = chunk ^ (row&7).
extern __shared__ char gsm[];
#define A_OFF(h) ((h) * 16384)
#define B_OFF(h) (32768 + (h) * 32768)
#define SMEM_TOTAL 98304

__global__ __launch_bounds__(512, 1) void gram_kernel(float* __restrict__ out) {
    const int tid  = threadIdx.x;
    const int wid  = tid >> 5;
    const int lane = tid & 31;
    const uint32_t smem_base = smem_u32(gsm);
    __shared__ unsigned s_rank;

    int by = 0, rem = blockIdx.x;
    while (rem >= NJ - (by >> 1)) { rem -= NJ - (by >> 1); by++; }
    const int j = (by >> 1) + rem;

    const uint8_t* __restrict__ xa = g_x8 + (size_t)(by * TILE) * D;
    const uint8_t* __restrict__ xb = g_x8 + (size_t)(j * 256) * D;

    // ---- Prefetch both K-halves (commit group per half) ----
    #pragma unroll
    for (int h = 0; h < 2; h++) {
        #pragma unroll
        for (int t = 0; t < 2; t++) {          // A: 128 rows x 8 chunks
            int i = tid + t * 512;
            int r = i >> 3, c = i & 7;
            cp_async16(smem_base + A_OFF(h) + r * 128 + ((c ^ (r & 7)) << 4),
                       xa + (size_t)r * D + h * 128 + c * 16);
        }
        #pragma unroll
        for (int t = 0; t < 4; t++) {          // B: 256 rows x 8 chunks
            int i = tid + t * 512;
            int r = i >> 3, c = i & 7;
            cp_async16(smem_base + B_OFF(h) + r * 128 + ((c ^ (r & 7)) << 4),
                       xb + (size_t)r * D + h * 128 + c * 16);
        }
        CP_COMMIT();
    }

    // ---- Warp tiling: 4 (m) x 4 (n); warp tile 32 x 64 ----
    const int warp_m = wid >> 2;
    const int warp_n = wid & 3;

    // Base-FREE fragment offsets; bits 4-6 hold (rx^c0)<<4 by construction,
    // so offset ^ (ks<<5) yields the swizzled chunk for K-step ks. smem_base
    // is added only at the ldmatrix call (safe for any base alignment).
    const uint32_t a_c0 = lane >> 4;
    uint32_t aoff[2];
    #pragma unroll
    for (int mt = 0; mt < 2; mt++) {
        int r = warp_m * 32 + mt * 16 + (lane & 15);
        aoff[mt] = (uint32_t)A_OFF(0) + (uint32_t)r * 128
                 + ((((uint32_t)(r & 7)) ^ a_c0) << 4);
    }
    const uint32_t b_c0 = (lane >> 3) & 1;
    uint32_t boff[4];
    #pragma unroll
    for (int nt2 = 0; nt2 < 4; nt2++) {
        int r = warp_n * 64 + nt2 * 16 + (lane >> 4) * 8 + (lane & 7);
        boff[nt2] = (uint32_t)B_OFF(0) + (uint32_t)r * 128
                  + ((((uint32_t)(r & 7)) ^ b_c0) << 4);
    }

    uint32_t acc[2][8][2];
    #pragma unroll
    for (int mt = 0; mt < 2; mt++)
        #pragma unroll
        for (int nt = 0; nt < 8; nt++) { acc[mt][nt][0] = 0u; acc[mt][nt][1] = 0u; }

    uint32_t af[2][2][4];    // [buf][mt][reg]
    uint32_t bf[2][8][2];    // [buf][nt][reg]

    #pragma unroll
    for (int h = 0; h < 2; h++) {
        if (h == 0) { CP_WAIT(1); } else { CP_WAIT(0); }
        __syncthreads();

        const uint32_t ahof = h * 16384;
        const uint32_t bhof = h * 32768;

        // Prologue: fragments for ks=0 of this half.
        #pragma unroll
        for (int mt = 0; mt < 2; mt++)
            ldmatrix_x4(af[0][mt][0], af[0][mt][1], af[0][mt][2], af[0][mt][3],
                        smem_base + (aoff[mt] + ahof));
        #pragma unroll
        for (int nt2 = 0; nt2 < 4; nt2++)
            ldmatrix_x4(bf[0][nt2*2][0], bf[0][nt2*2][1],
                        bf[0][nt2*2+1][0], bf[0][nt2*2+1][1],
                        smem_base + (boff[nt2] + bhof));

        #pragma unroll
        for (int ks = 0; ks < 4; ks++) {
            const int p = ks & 1;
            if (ks < 3) {                       // prefetch next K-step's frags
                const uint32_t kx = (uint32_t)(ks + 1) << 5;
                #pragma unroll
                for (int mt = 0; mt < 2; mt++)
                    ldmatrix_x4(af[p^1][mt][0], af[p^1][mt][1],
                                af[p^1][mt][2], af[p^1][mt][3],
                                smem_base + ((aoff[mt] + ahof) ^ kx));
                #pragma unroll
                for (int nt2 = 0; nt2 < 4; nt2++)
                    ldmatrix_x4(bf[p^1][nt2*2][0], bf[p^1][nt2*2][1],
                                bf[p^1][nt2*2+1][0], bf[p^1][nt2*2+1][1],
                                smem_base + ((boff[nt2] + bhof) ^ kx));
            }
            #pragma unroll
            for (int mt = 0; mt < 2; mt++)
                #pragma unroll
                for (int nt = 0; nt < 8; nt++)
                    mma_fp8_h(acc[mt][nt], af[p][mt], bf[p][nt]);
        }
        if (h == 0) __syncthreads();
    }

    // ---- Fused epilogue: e = exp(4*min(c-1,0)); include iff gcol > grow ----
    const int gid = lane >> 2;
    const int tig = lane & 3;
    const int grow0 = by * TILE + warp_m * 32 + gid;
    const int gcol0 = j * 256 + warp_n * 64 + tig * 2;
    float s = 0.0f;
    #pragma unroll
    for (int mt = 0; mt < 2; mt++) {
        #pragma unroll
        for (int nt = 0; nt < 8; nt++) {
            float2 f0 = __half22float2(*(const __half2*)&acc[mt][nt][0]);
            float2 f1 = __half22float2(*(const __half2*)&acc[mt][nt][1]);
            const int gr = grow0 + mt * 16;
            const int gc = gcol0 + nt * 8;
            float e;
            e = __expf(4.0f * fminf(f0.x - 1.0f, 0.0f)); if (gc     > gr    ) s += e;
            e = __expf(4.0f * fminf(f0.y - 1.0f, 0.0f)); if (gc + 1 > gr    ) s += e;
            e = __expf(4.0f * fminf(f1.x - 1.0f, 0.0f)); if (gc     > gr + 8) s += e;
            e = __expf(4.0f * fminf(f1.y - 1.0f, 0.0f)); if (gc + 1 > gr + 8) s += e;
        }
    }
    s = block_reduce<16>(s);
    if (tid == 0) g_part[blockIdx.x] = s;

    // ---- Fused final reduction in the last-arriving CTA (fixed order) ----
    __threadfence();
    if (tid == 0) s_rank = atomicAdd(&g_done, 1u);
    __syncthreads();
    if (s_rank == NST - 1) {
        float sa = 0.0f, su = 0.0f;
        for (int i = tid; i < BROWS; i += 512) sa += g_align[i];
        for (int i = tid; i < NST;   i += 512) su += g_part[i];
        sa = block_reduce<16>(sa);
        su = block_reduce<16>(su);
        if (tid == 0) {
            double align_loss   = (double)sa / (double)BROWS;
            double uniform_loss = 2.0 * (double)su / ((double)NTOT * (double)(NTOT - 1));
            out[0] = (float)(align_loss + uniform_loss);
        }
    }
}

// ---------------------------------------------------------------------------
extern "C" void kernel_launch(void* const* d_in, const int* in_sizes, int n_in,
                              void* d_out, int out_size) {
    const float* a = (const float*)d_in[0];
    const float* b = (const float*)d_in[1];
    float* out = (float*)d_out;

    cudaFuncSetAttribute(gram_kernel,
                         cudaFuncAttributeMaxDynamicSharedMemorySize, SMEM_TOTAL);

    normalize_kernel<<<BROWS / 8, 256>>>(a, b);
    gram_kernel<<<NST, 512, SMEM_TOTAL>>>(out);
}

// round 12
// speedup vs baseline: 1.8432x; 1.0242x over previous
#include <cuda_runtime.h>
#include <cuda_fp16.h>
#include <cstdint>
#include <math.h>

#define D      256
#define BROWS  4096
#define NTOT   8192
#define TILE   128
#define NB     (NTOT / TILE)            // 64 row tiles
#define NJ     (NB / 2)                 // 32 column super-tiles
#define NST    1056                     // upper-tri super-tiles

// ---------------------------------------------------------------------------
__device__ uint8_t g_x8[NTOT * D];      // normalized [a;b], e4m3 (2 MB)
__device__ float g_align[BROWS];
__device__ float g_part[NST];
__device__ unsigned int g_done;

// ---------------------------------------------------------------------------
__device__ __forceinline__ uint32_t smem_u32(const void* p) {
    uint32_t a;
    asm("{ .reg .u64 t; cvta.to.shared.u64 t, %1; cvt.u32.u64 %0, t; }" : "=r"(a) : "l"(p));
    return a;
}
__device__ __forceinline__ void cp_async16(uint32_t dst, const void* src) {
    asm volatile("cp.async.cg.shared.global [%0], [%1], 16;" :: "r"(dst), "l"(src));
}
#define CP_COMMIT() asm volatile("cp.async.commit_group;" ::: "memory")
#define CP_WAIT(n)  asm volatile("cp.async.wait_group %0;" :: "n"(n) : "memory")

__device__ __forceinline__ void ldmatrix_x4(uint32_t& r0, uint32_t& r1,
                                            uint32_t& r2, uint32_t& r3, uint32_t addr) {
    asm volatile("ldmatrix.sync.aligned.m8n8.x4.shared.b16 {%0,%1,%2,%3}, [%4];"
                 : "=r"(r0), "=r"(r1), "=r"(r2), "=r"(r3) : "r"(addr));
}
// fp8 e4m3 MMA, K=32, fp16 accumulator (fastest measured legacy-path variant).
__device__ __forceinline__ void mma_fp8_h(uint32_t* c, const uint32_t* a, const uint32_t* b) {
    asm volatile(
        "mma.sync.aligned.m16n8k32.row.col.f16.e4m3.e4m3.f16 "
        "{%0,%1}, {%2,%3,%4,%5}, {%6,%7}, {%0,%1};"
        : "+r"(c[0]), "+r"(c[1])
        : "r"(a[0]), "r"(a[1]), "r"(a[2]), "r"(a[3]), "r"(b[0]), "r"(b[1]));
}
__device__ __forceinline__ uint32_t pack_e4m3(float e0, float e1, float e2, float e3) {
    uint32_t out;
    asm("{ .reg .b16 lo, hi;\n\t"
        "cvt.rn.satfinite.e4m3x2.f32 lo, %2, %1;\n\t"
        "cvt.rn.satfinite.e4m3x2.f32 hi, %4, %3;\n\t"
        "mov.b32 %0, {lo, hi}; }"
        : "=r"(out) : "f"(e0), "f"(e1), "f"(e2), "f"(e3));
    return out;
}

// ---------------------------------------------------------------------------
template <int NWARP>
__device__ __forceinline__ float block_reduce(float v) {
    __shared__ float sh[NWARP];
    #pragma unroll
    for (int o = 16; o > 0; o >>= 1) v += __shfl_down_sync(0xffffffffu, v, o);
    if ((threadIdx.x & 31) == 0) sh[threadIdx.x >> 5] = v;
    __syncthreads();
    if (threadIdx.x == 0) {
        float t = 0.f;
        #pragma unroll
        for (int i = 0; i < NWARP; i++) t += sh[i];
        sh[0] = t;
    }
    __syncthreads();
    float r = sh[0];
    __syncthreads();
    return r;
}
__device__ __forceinline__ float warp_allreduce(float v) {
    #pragma unroll
    for (int o = 16; o > 0; o >>= 1) v += __shfl_xor_sync(0xffffffffu, v, o);
    return v;
}

// ---------------------------------------------------------------------------
// Kernel 1: warp-per-row L2 normalize -> e4m3; resets g_done.
__global__ __launch_bounds__(256) void normalize_kernel(
    const float* __restrict__ a, const float* __restrict__ b) {
    if (blockIdx.x == 0 && threadIdx.x == 0) g_done = 0u;

    const int lane = threadIdx.x & 31;
    const int row  = blockIdx.x * 8 + (threadIdx.x >> 5);

    const float4* ar = (const float4*)(a + (size_t)row * D);
    const float4* br = (const float4*)(b + (size_t)row * D);
    float4 a0 = ar[lane], a1 = ar[lane + 32];
    float4 b0 = br[lane], b1 = br[lane + 32];

    float sa = warp_allreduce(a0.x*a0.x + a0.y*a0.y + a0.z*a0.z + a0.w*a0.w +
                              a1.x*a1.x + a1.y*a1.y + a1.z*a1.z + a1.w*a1.w);
    float sb = warp_allreduce(b0.x*b0.x + b0.y*b0.y + b0.z*b0.z + b0.w*b0.w +
                              b1.x*b1.x + b1.y*b1.y + b1.z*b1.z + b1.w*b1.w);

    float ra = 1.0f / fmaxf(sqrtf(sa), 1e-12f);
    float rb = 1.0f / fmaxf(sqrtf(sb), 1e-12f);

    a0.x *= ra; a0.y *= ra; a0.z *= ra; a0.w *= ra;
    a1.x *= ra; a1.y *= ra; a1.z *= ra; a1.w *= ra;
    b0.x *= rb; b0.y *= rb; b0.z *= rb; b0.w *= rb;
    b1.x *= rb; b1.y *= rb; b1.z *= rb; b1.w *= rb;

    uint32_t* xa = (uint32_t*)g_x8 + (size_t)row * 64;
    uint32_t* xb = (uint32_t*)g_x8 + (size_t)(BROWS + row) * 64;
    xa[lane]      = pack_e4m3(a0.x, a0.y, a0.z, a0.w);
    xa[lane + 32] = pack_e4m3(a1.x, a1.y, a1.z, a1.w);
    xb[lane]      = pack_e4m3(b0.x, b0.y, b0.z, b0.w);
    xb[lane + 32] = pack_e4m3(b1.x, b1.y, b1.z, b1.w);

    float dx0 = a0.x-b0.x, dy0 = a0.y-b0.y, dz0 = a0.z-b0.z, dw0 = a0.w-b0.w;
    float dx1 = a1.x-b1.x, dy1 = a1.y-b1.y, dz1 = a1.z-b1.z, dw1 = a1.w-b1.w;
    float sd = warp_allreduce(dx0*dx0 + dy0*dy0 + dz0*dz0 + dw0*dw0 +
                              dx1*dx1 + dy1*dy1 + dz1*dz1 + dw1*dw1);
    if (lane == 0) g_align[row] = sd;
}

// ---------------------------------------------------------------------------
// Kernel 2: 128x256 fp8 super-tile Gram (R6 loop verbatim), K-half
// double-buffered cp.async, fused exp epilogue, fused last-CTA final reduce.
// Smem per half: A @ h*16384, B @ 32768 + h*32768. Row pitch 128 B
// (8 chunks); swizzle chunk' = chunk ^ (row&7).
extern __shared__ char gsm[];
#define A_OFF(h) ((h) * 16384)
#define B_OFF(h) (32768 + (h) * 32768)
#define SMEM_TOTAL 98304

__global__ __launch_bounds__(512, 1) void gram_kernel(float* __restrict__ out) {
    const int tid  = threadIdx.x;
    const int wid  = tid >> 5;
    const int lane = tid & 31;
    const uint32_t smem_base = smem_u32(gsm);
    __shared__ unsigned s_rank;

    int by = 0, rem = blockIdx.x;
    while (rem >= NJ - (by >> 1)) { rem -= NJ - (by >> 1); by++; }
    const int j = (by >> 1) + rem;

    const uint8_t* __restrict__ xa = g_x8 + (size_t)(by * TILE) * D;
    const uint8_t* __restrict__ xb = g_x8 + (size_t)(j * 256) * D;

    // ---- Prefetch both K-halves (commit group per half) ----
    #pragma unroll
    for (int h = 0; h < 2; h++) {
        #pragma unroll
        for (int t = 0; t < 2; t++) {          // A: 128 rows x 8 chunks
            int i = tid + t * 512;
            int r = i >> 3, c = i & 7;
            cp_async16(smem_base + A_OFF(h) + r * 128 + ((c ^ (r & 7)) << 4),
                       xa + (size_t)r * D + h * 128 + c * 16);
        }
        #pragma unroll
        for (int t = 0; t < 4; t++) {          // B: 256 rows x 8 chunks
            int i = tid + t * 512;
            int r = i >> 3, c = i & 7;
            cp_async16(smem_base + B_OFF(h) + r * 128 + ((c ^ (r & 7)) << 4),
                       xb + (size_t)r * D + h * 128 + c * 16);
        }
        CP_COMMIT();
    }

    // ---- Warp tiling: 4 (m) x 4 (n); warp tile 32 x 64 ----
    const int warp_m = wid >> 2;
    const int warp_n = wid & 3;

    uint32_t a_row[2], a_rx[2];
    #pragma unroll
    for (int mt = 0; mt < 2; mt++) {
        int r = warp_m * 32 + mt * 16 + (lane & 15);
        a_row[mt] = (uint32_t)r * 128;
        a_rx[mt]  = r & 7;
    }
    const uint32_t a_c0 = lane >> 4;

    uint32_t b_row[4], b_rx[4];
    #pragma unroll
    for (int nt2 = 0; nt2 < 4; nt2++) {
        int r = warp_n * 64 + nt2 * 16 + (lane >> 4) * 8 + (lane & 7);
        b_row[nt2] = (uint32_t)r * 128;
        b_rx[nt2]  = r & 7;
    }
    const uint32_t b_c0 = (lane >> 3) & 1;

    uint32_t acc[2][8][2];                 // fp16x2 accumulators
    #pragma unroll
    for (int mt = 0; mt < 2; mt++)
        #pragma unroll
        for (int nt = 0; nt < 8; nt++) { acc[mt][nt][0] = 0u; acc[mt][nt][1] = 0u; }

    #pragma unroll
    for (int h = 0; h < 2; h++) {
        if (h == 0) { CP_WAIT(1); } else { CP_WAIT(0); }
        __syncthreads();

        const uint32_t abase = smem_base + A_OFF(h);
        const uint32_t bbase = smem_base + B_OFF(h);

        #pragma unroll
        for (int ks = 0; ks < 4; ks++) {
            uint32_t af[2][4];
            #pragma unroll
            for (int mt = 0; mt < 2; mt++)
                ldmatrix_x4(af[mt][0], af[mt][1], af[mt][2], af[mt][3],
                            abase + a_row[mt] + (((2 * ks + a_c0) ^ a_rx[mt]) << 4));
            uint32_t bf[8][2];
            #pragma unroll
            for (int nt2 = 0; nt2 < 4; nt2++) {
                uint32_t r0, r1, r2, r3;
                ldmatrix_x4(r0, r1, r2, r3,
                            bbase + b_row[nt2] + (((2 * ks + b_c0) ^ b_rx[nt2]) << 4));
                bf[nt2 * 2 + 0][0] = r0; bf[nt2 * 2 + 0][1] = r1;
                bf[nt2 * 2 + 1][0] = r2; bf[nt2 * 2 + 1][1] = r3;
            }
            #pragma unroll
            for (int mt = 0; mt < 2; mt++)
                #pragma unroll
                for (int nt = 0; nt < 8; nt++)
                    mma_fp8_h(acc[mt][nt], af[mt], bf[nt]);
        }
        if (h == 0) __syncthreads();
    }

    // ---- Fused epilogue: e = exp(4*min(c-1,0)); include iff gcol > grow ----
    const int gid = lane >> 2;
    const int tig = lane & 3;
    const int grow0 = by * TILE + warp_m * 32 + gid;
    const int gcol0 = j * 256 + warp_n * 64 + tig * 2;
    float s = 0.0f;
    #pragma unroll
    for (int mt = 0; mt < 2; mt++) {
        #pragma unroll
        for (int nt = 0; nt < 8; nt++) {
            float2 f0 = __half22float2(*(const __half2*)&acc[mt][nt][0]);
            float2 f1 = __half22float2(*(const __half2*)&acc[mt][nt][1]);
            const int gr = grow0 + mt * 16;
            const int gc = gcol0 + nt * 8;
            float e;
            e = __expf(4.0f * fminf(f0.x - 1.0f, 0.0f)); if (gc     > gr    ) s += e;
            e = __expf(4.0f * fminf(f0.y - 1.0f, 0.0f)); if (gc + 1 > gr    ) s += e;
            e = __expf(4.0f * fminf(f1.x - 1.0f, 0.0f)); if (gc     > gr + 8) s += e;
            e = __expf(4.0f * fminf(f1.y - 1.0f, 0.0f)); if (gc + 1 > gr + 8) s += e;
        }
    }
    s = block_reduce<16>(s);
    if (tid == 0) g_part[blockIdx.x] = s;

    // ---- Fused final reduction in the last-arriving CTA (fixed order) ----
    __threadfence();
    if (tid == 0) s_rank = atomicAdd(&g_done, 1u);
    __syncthreads();
    if (s_rank == NST - 1) {
        float sa = 0.0f, su = 0.0f;
        for (int i = tid; i < BROWS; i += 512) sa += g_align[i];
        for (int i = tid; i < NST;   i += 512) su += g_part[i];
        sa = block_reduce<16>(sa);
        su = block_reduce<16>(su);
        if (tid == 0) {
            double align_loss   = (double)sa / (double)BROWS;
            double uniform_loss = 2.0 * (double)su / ((double)NTOT * (double)(NTOT - 1));
            out[0] = (float)(align_loss + uniform_loss);
        }
    }
}

// ---------------------------------------------------------------------------
extern "C" void kernel_launch(void* const* d_in, const int* in_sizes, int n_in,
                              void* d_out, int out_size) {
    const float* a = (const float*)d_in[0];
    const float* b = (const float*)d_in[1];
    float* out = (float*)d_out;

    cudaFuncSetAttribute(gram_kernel,
                         cudaFuncAttributeMaxDynamicSharedMemorySize, SMEM_TOTAL);

    normalize_kernel<<<BROWS / 8, 256>>>(a, b);
    gram_kernel<<<NST, 512, SMEM_TOTAL>>>(out);
}

// round 13
// speedup vs baseline: 2.0420x; 1.1078x over previous
#include <cuda_runtime.h>
#include <cuda_fp16.h>
#include <cstdint>
#include <math.h>

#define D      256
#define BROWS  4096
#define NTOT   8192
#define TILE   128
#define NB     (NTOT / TILE)          // 64 row tiles
#define NJ     (NB / 2)               // 32 column super-tiles (256 cols)
#define NST    1056                   // upper-tri super-tiles

// ---------------------------------------------------------------------------
__device__ uint8_t g_x8[NTOT * D];    // normalized [a;b], e4m3 (2 MB)
__device__ float g_align[BROWS];
__device__ float g_part[NST];

// ---------------------------------------------------------------------------
__device__ __forceinline__ uint32_t smem_u32(const void* p) {
    uint32_t a;
    asm("{ .reg .u64 t; cvta.to.shared.u64 t, %1; cvt.u32.u64 %0, t; }" : "=r"(a) : "l"(p));
    return a;
}
__device__ __forceinline__ void cp_async16(uint32_t dst, const void* src) {
    asm volatile("cp.async.cg.shared.global [%0], [%1], 16;" :: "r"(dst), "l"(src));
}
#define CP_COMMIT() asm volatile("cp.async.commit_group;" ::: "memory")
#define CP_WAIT(n)  asm volatile("cp.async.wait_group %0;" :: "n"(n) : "memory")

__device__ __forceinline__ void ldmatrix_x4(uint32_t& r0, uint32_t& r1,
                                            uint32_t& r2, uint32_t& r3, uint32_t addr) {
    asm volatile("ldmatrix.sync.aligned.m8n8.x4.shared.b16 {%0,%1,%2,%3}, [%4];"
                 : "=r"(r0), "=r"(r1), "=r"(r2), "=r"(r3) : "r"(addr));
}
// fp8 e4m3 MMA, K=32, **fp16 accumulator** (2 regs = 4 halves).
__device__ __forceinline__ void mma_fp8_h(uint32_t* c, const uint32_t* a, const uint32_t* b) {
    asm volatile(
        "mma.sync.aligned.m16n8k32.row.col.f16.e4m3.e4m3.f16 "
        "{%0,%1}, {%2,%3,%4,%5}, {%6,%7}, {%0,%1};"
        : "+r"(c[0]), "+r"(c[1])
        : "r"(a[0]), "r"(a[1]), "r"(a[2]), "r"(a[3]), "r"(b[0]), "r"(b[1]));
}
// pack 4 floats -> 4 e4m3 bytes
__device__ __forceinline__ uint32_t pack_e4m3(float e0, float e1, float e2, float e3) {
    uint32_t out;
    asm("{ .reg .b16 lo, hi;\n\t"
        "cvt.rn.satfinite.e4m3x2.f32 lo, %2, %1;\n\t"
        "cvt.rn.satfinite.e4m3x2.f32 hi, %4, %3;\n\t"
        "mov.b32 %0, {lo, hi}; }"
        : "=r"(out) : "f"(e0), "f"(e1), "f"(e2), "f"(e3));
    return out;
}

// ---------------------------------------------------------------------------
template <int NWARP>
__device__ __forceinline__ float block_reduce(float v) {
    __shared__ float sh[NWARP];
    #pragma unroll
    for (int o = 16; o > 0; o >>= 1) v += __shfl_down_sync(0xffffffffu, v, o);
    if ((threadIdx.x & 31) == 0) sh[threadIdx.x >> 5] = v;
    __syncthreads();
    if (threadIdx.x == 0) {
        float t = 0.f;
        #pragma unroll
        for (int i = 0; i < NWARP; i++) t += sh[i];
        sh[0] = t;
    }
    __syncthreads();
    float r = sh[0];
    __syncthreads();
    return r;
}
__device__ __forceinline__ float warp_allreduce(float v) {
    #pragma unroll
    for (int o = 16; o > 0; o >>= 1) v += __shfl_xor_sync(0xffffffffu, v, o);
    return v;
}

// ---------------------------------------------------------------------------
// Kernel 1: warp-per-row L2 normalize -> e4m3, per-row align term.
__global__ __launch_bounds__(256) void normalize_kernel(
    const float* __restrict__ a, const float* __restrict__ b) {
    const int lane = threadIdx.x & 31;
    const int row  = blockIdx.x * 8 + (threadIdx.x >> 5);

    const float4* ar = (const float4*)(a + (size_t)row * D);
    const float4* br = (const float4*)(b + (size_t)row * D);
    float4 a0 = ar[lane], a1 = ar[lane + 32];
    float4 b0 = br[lane], b1 = br[lane + 32];

    float sa = warp_allreduce(a0.x*a0.x + a0.y*a0.y + a0.z*a0.z + a0.w*a0.w +
                              a1.x*a1.x + a1.y*a1.y + a1.z*a1.z + a1.w*a1.w);
    float sb = warp_allreduce(b0.x*b0.x + b0.y*b0.y + b0.z*b0.z + b0.w*b0.w +
                              b1.x*b1.x + b1.y*b1.y + b1.z*b1.z + b1.w*b1.w);

    float ra = 1.0f / fmaxf(sqrtf(sa), 1e-12f);
    float rb = 1.0f / fmaxf(sqrtf(sb), 1e-12f);

    a0.x *= ra; a0.y *= ra; a0.z *= ra; a0.w *= ra;
    a1.x *= ra; a1.y *= ra; a1.z *= ra; a1.w *= ra;
    b0.x *= rb; b0.y *= rb; b0.z *= rb; b0.w *= rb;
    b1.x *= rb; b1.y *= rb; b1.z *= rb; b1.w *= rb;

    uint32_t* xa = (uint32_t*)g_x8 + (size_t)row * 64;
    uint32_t* xb = (uint32_t*)g_x8 + (size_t)(BROWS + row) * 64;
    xa[lane]      = pack_e4m3(a0.x, a0.y, a0.z, a0.w);
    xa[lane + 32] = pack_e4m3(a1.x, a1.y, a1.z, a1.w);
    xb[lane]      = pack_e4m3(b0.x, b0.y, b0.z, b0.w);
    xb[lane + 32] = pack_e4m3(b1.x, b1.y, b1.z, b1.w);

    float dx0 = a0.x-b0.x, dy0 = a0.y-b0.y, dz0 = a0.z-b0.z, dw0 = a0.w-b0.w;
    float dx1 = a1.x-b1.x, dy1 = a1.y-b1.y, dz1 = a1.z-b1.z, dw1 = a1.w-b1.w;
    float sd = warp_allreduce(dx0*dx0 + dy0*dy0 + dz0*dz0 + dw0*dw0 +
                              dx1*dx1 + dy1*dy1 + dz1*dz1 + dw1*dw1);
    if (lane == 0) g_align[row] = sd;
}

// ---------------------------------------------------------------------------
// Kernel 2: 128x256 fp8 super-tile Gram (fp16 acc), double-buffered K-halves.
extern __shared__ char gsm[];
#define A_OFF(h) ((h) * 16384)
#define B_OFF(h) (32768 + (h) * 32768)
#define SMEM_TOTAL 98304

__global__ __launch_bounds__(512, 1) void gram_kernel() {
    const int tid  = threadIdx.x;
    const int wid  = tid >> 5;
    const int lane = tid & 31;
    const uint32_t smem_base = smem_u32(gsm);

    int by = 0, rem = blockIdx.x;
    while (rem >= NJ - (by >> 1)) { rem -= NJ - (by >> 1); by++; }
    const int j = (by >> 1) + rem;

    const uint8_t* __restrict__ xa = g_x8 + (size_t)(by * TILE) * D;
    const uint8_t* __restrict__ xb = g_x8 + (size_t)(j * 256) * D;

    #pragma unroll
    for (int h = 0; h < 2; h++) {
        #pragma unroll
        for (int t = 0; t < 2; t++) {          // A: 128 rows x 8 chunks
            int i = tid + t * 512;
            int r = i >> 3, c = i & 7;
            cp_async16(smem_base + A_OFF(h) + r * 128 + ((c ^ (r & 7)) << 4),
                       xa + (size_t)r * D + h * 128 + c * 16);
        }
        #pragma unroll
        for (int t = 0; t < 4; t++) {          // B: 256 rows x 8 chunks
            int i = tid + t * 512;
            int r = i >> 3, c = i & 7;
            cp_async16(smem_base + B_OFF(h) + r * 128 + ((c ^ (r & 7)) << 4),
                       xb + (size_t)r * D + h * 128 + c * 16);
        }
        CP_COMMIT();
    }

    const int warp_m = wid >> 2;
    const int warp_n = wid & 3;

    uint32_t a_row[2], a_rx[2];
    #pragma unroll
    for (int mt = 0; mt < 2; mt++) {
        int r = warp_m * 32 + mt * 16 + (lane & 15);
        a_row[mt] = (uint32_t)r * 128;
        a_rx[mt]  = r & 7;
    }
    const uint32_t a_c0 = lane >> 4;

    uint32_t b_row[4], b_rx[4];
    #pragma unroll
    for (int nt2 = 0; nt2 < 4; nt2++) {
        int r = warp_n * 64 + nt2 * 16 + (lane >> 4) * 8 + (lane & 7);
        b_row[nt2] = (uint32_t)r * 128;
        b_rx[nt2]  = r & 7;
    }
    const uint32_t b_c0 = (lane >> 3) & 1;

    uint32_t acc[2][8][2];                 // fp16x2 accumulators
    #pragma unroll
    for (int mt = 0; mt < 2; mt++)
        #pragma unroll
        for (int nt = 0; nt < 8; nt++) { acc[mt][nt][0] = 0u; acc[mt][nt][1] = 0u; }

    #pragma unroll
    for (int h = 0; h < 2; h++) {
        if (h == 0) { CP_WAIT(1); } else { CP_WAIT(0); }
        __syncthreads();

        const uint32_t abase = smem_base + A_OFF(h);
        const uint32_t bbase = smem_base + B_OFF(h);

        #pragma unroll
        for (int ks = 0; ks < 4; ks++) {
            uint32_t af[2][4];
            #pragma unroll
            for (int mt = 0; mt < 2; mt++)
                ldmatrix_x4(af[mt][0], af[mt][1], af[mt][2], af[mt][3],
                            abase + a_row[mt] + (((2 * ks + a_c0) ^ a_rx[mt]) << 4));
            uint32_t bf[8][2];
            #pragma unroll
            for (int nt2 = 0; nt2 < 4; nt2++) {
                uint32_t r0, r1, r2, r3;
                ldmatrix_x4(r0, r1, r2, r3,
                            bbase + b_row[nt2] + (((2 * ks + b_c0) ^ b_rx[nt2]) << 4));
                bf[nt2 * 2 + 0][0] = r0; bf[nt2 * 2 + 0][1] = r1;
                bf[nt2 * 2 + 1][0] = r2; bf[nt2 * 2 + 1][1] = r3;
            }
            #pragma unroll
            for (int mt = 0; mt < 2; mt++)
                #pragma unroll
                for (int nt = 0; nt < 8; nt++)
                    mma_fp8_h(acc[mt][nt], af[mt], bf[nt]);
        }
        if (h == 0) __syncthreads();
    }

    // ---- Fused epilogue: e = exp(4*min(c-1,0)); include iff gcol > grow ----
    // acc reg0 = {(r, c), (r, c+1)}, reg1 = {(r+8, c), (r+8, c+1)}
    const int gid = lane >> 2;
    const int tig = lane & 3;
    const int grow0 = by * TILE + warp_m * 32 + gid;
    const int gcol0 = j * 256 + warp_n * 64 + tig * 2;
    float s = 0.0f;
    #pragma unroll
    for (int mt = 0; mt < 2; mt++) {
        #pragma unroll
        for (int nt = 0; nt < 8; nt++) {
            float2 f0 = __half22float2(*(const __half2*)&acc[mt][nt][0]);
            float2 f1 = __half22float2(*(const __half2*)&acc[mt][nt][1]);
            const int gr = grow0 + mt * 16;
            const int gc = gcol0 + nt * 8;
            float e;
            e = __expf(4.0f * fminf(f0.x - 1.0f, 0.0f)); if (gc     > gr    ) s += e;
            e = __expf(4.0f * fminf(f0.y - 1.0f, 0.0f)); if (gc + 1 > gr    ) s += e;
            e = __expf(4.0f * fminf(f1.x - 1.0f, 0.0f)); if (gc     > gr + 8) s += e;
            e = __expf(4.0f * fminf(f1.y - 1.0f, 0.0f)); if (gc + 1 > gr + 8) s += e;
        }
    }

    s = block_reduce<16>(s);
    if (tid == 0) g_part[blockIdx.x] = s;
}

// ---------------------------------------------------------------------------
__global__ __launch_bounds__(256) void finalize_kernel(float* __restrict__ out) {
    float sa = 0.0f, su = 0.0f;
    for (int i = threadIdx.x; i < BROWS; i += 256) sa += g_align[i];
    for (int i = threadIdx.x; i < NST;   i += 256) su += g_part[i];
    sa = block_reduce<8>(sa);
    su = block_reduce<8>(su);
    if (threadIdx.x == 0) {
        double align_loss   = (double)sa / (double)BROWS;
        double uniform_loss = 2.0 * (double)su / ((double)NTOT * (double)(NTOT - 1));
        out[0] = (float)(align_loss + uniform_loss);
    }
}

// ---------------------------------------------------------------------------
extern "C" void kernel_launch(void* const* d_in, const int* in_sizes, int n_in,
                              void* d_out, int out_size) {
    const float* a = (const float*)d_in[0];
    const float* b = (const float*)d_in[1];
    float* out = (float*)d_out;

    cudaFuncSetAttribute(gram_kernel,
                         cudaFuncAttributeMaxDynamicSharedMemorySize, SMEM_TOTAL);

    normalize_kernel<<<BROWS / 8, 256>>>(a, b);
    gram_kernel<<<NST, 512, SMEM_TOTAL>>>();
    finalize_kernel<<<1, 256>>>(out);
}

// round 16
// speedup vs baseline: 2.3029x; 1.1278x over previous
#include <cuda_runtime.h>
#include <cuda_fp16.h>
#include <cstdint>
#include <math.h>

#define D      256
#define BROWS  4096
#define NTOT   8192
#define TILE   128
#define NB     (NTOT / TILE)          // 64 row/col tiles
#define NTILES (NB * (NB + 1) / 2)    // 2080 upper-tri tiles

// ---------------------------------------------------------------------------
__device__ uint8_t g_x8[NTOT * D];    // normalized [a;b], e4m3 (2 MB)
__device__ float g_align[BROWS];
__device__ float g_part[NTILES];

// ---------------------------------------------------------------------------
__device__ __forceinline__ uint32_t smem_u32(const void* p) {
    uint32_t a;
    asm("{ .reg .u64 t; cvta.to.shared.u64 t, %1; cvt.u32.u64 %0, t; }" : "=r"(a) : "l"(p));
    return a;
}
__device__ __forceinline__ void cp_async16(uint32_t dst, const void* src) {
    asm volatile("cp.async.cg.shared.global [%0], [%1], 16;" :: "r"(dst), "l"(src));
}
#define CP_COMMIT() asm volatile("cp.async.commit_group;" ::: "memory")
#define CP_WAIT(n)  asm volatile("cp.async.wait_group %0;" :: "n"(n) : "memory")

__device__ __forceinline__ void ldmatrix_x4(uint32_t& r0, uint32_t& r1,
                                            uint32_t& r2, uint32_t& r3, uint32_t addr) {
    asm volatile("ldmatrix.sync.aligned.m8n8.x4.shared.b16 {%0,%1,%2,%3}, [%4];"
                 : "=r"(r0), "=r"(r1), "=r"(r2), "=r"(r3) : "r"(addr));
}
// fp8 e4m3 MMA, K=32, fp16 accumulator (fastest measured legacy-path variant).
__device__ __forceinline__ void mma_fp8_h(uint32_t* c, const uint32_t* a, const uint32_t* b) {
    asm volatile(
        "mma.sync.aligned.m16n8k32.row.col.f16.e4m3.e4m3.f16 "
        "{%0,%1}, {%2,%3,%4,%5}, {%6,%7}, {%0,%1};"
        : "+r"(c[0]), "+r"(c[1])
        : "r"(a[0]), "r"(a[1]), "r"(a[2]), "r"(a[3]), "r"(b[0]), "r"(b[1]));
}
__device__ __forceinline__ uint32_t pack_e4m3(float e0, float e1, float e2, float e3) {
    uint32_t out;
    asm("{ .reg .b16 lo, hi;\n\t"
        "cvt.rn.satfinite.e4m3x2.f32 lo, %2, %1;\n\t"
        "cvt.rn.satfinite.e4m3x2.f32 hi, %4, %3;\n\t"
        "mov.b32 %0, {lo, hi}; }"
        : "=r"(out) : "f"(e0), "f"(e1), "f"(e2), "f"(e3));
    return out;
}

// ---------------------------------------------------------------------------
template <int NWARP>
__device__ __forceinline__ float block_reduce(float v) {
    __shared__ float sh[NWARP];
    #pragma unroll
    for (int o = 16; o > 0; o >>= 1) v += __shfl_down_sync(0xffffffffu, v, o);
    if ((threadIdx.x & 31) == 0) sh[threadIdx.x >> 5] = v;
    __syncthreads();
    if (threadIdx.x == 0) {
        float t = 0.f;
        #pragma unroll
        for (int i = 0; i < NWARP; i++) t += sh[i];
        sh[0] = t;
    }
    __syncthreads();
    float r = sh[0];
    __syncthreads();
    return r;
}
__device__ __forceinline__ float warp_allreduce(float v) {
    #pragma unroll
    for (int o = 16; o > 0; o >>= 1) v += __shfl_xor_sync(0xffffffffu, v, o);
    return v;
}

// ---------------------------------------------------------------------------
// Kernel 1: warp-per-row L2 normalize -> e4m3, per-row align term.
__global__ __launch_bounds__(256) void normalize_kernel(
    const float* __restrict__ a, const float* __restrict__ b) {
    const int lane = threadIdx.x & 31;
    const int row  = blockIdx.x * 8 + (threadIdx.x >> 5);

    const float4* ar = (const float4*)(a + (size_t)row * D);
    const float4* br = (const float4*)(b + (size_t)row * D);
    float4 a0 = ar[lane], a1 = ar[lane + 32];
    float4 b0 = br[lane], b1 = br[lane + 32];

    float sa = warp_allreduce(a0.x*a0.x + a0.y*a0.y + a0.z*a0.z + a0.w*a0.w +
                              a1.x*a1.x + a1.y*a1.y + a1.z*a1.z + a1.w*a1.w);
    float sb = warp_allreduce(b0.x*b0.x + b0.y*b0.y + b0.z*b0.z + b0.w*b0.w +
                              b1.x*b1.x + b1.y*b1.y + b1.z*b1.z + b1.w*b1.w);

    float ra = 1.0f / fmaxf(sqrtf(sa), 1e-12f);
    float rb = 1.0f / fmaxf(sqrtf(sb), 1e-12f);

    a0.x *= ra; a0.y *= ra; a0.z *= ra; a0.w *= ra;
    a1.x *= ra; a1.y *= ra; a1.z *= ra; a1.w *= ra;
    b0.x *= rb; b0.y *= rb; b0.z *= rb; b0.w *= rb;
    b1.x *= rb; b1.y *= rb; b1.z *= rb; b1.w *= rb;

    uint32_t* xa = (uint32_t*)g_x8 + (size_t)row * 64;
    uint32_t* xb = (uint32_t*)g_x8 + (size_t)(BROWS + row) * 64;
    xa[lane]      = pack_e4m3(a0.x, a0.y, a0.z, a0.w);
    xa[lane + 32] = pack_e4m3(a1.x, a1.y, a1.z, a1.w);
    xb[lane]      = pack_e4m3(b0.x, b0.y, b0.z, b0.w);
    xb[lane + 32] = pack_e4m3(b1.x, b1.y, b1.z, b1.w);

    float dx0 = a0.x-b0.x, dy0 = a0.y-b0.y, dz0 = a0.z-b0.z, dw0 = a0.w-b0.w;
    float dx1 = a1.x-b1.x, dy1 = a1.y-b1.y, dz1 = a1.z-b1.z, dw1 = a1.w-b1.w;
    float sd = warp_allreduce(dx0*dx0 + dy0*dy0 + dz0*dz0 + dw0*dw0 +
                              dx1*dx1 + dy1*dy1 + dz1*dz1 + dw1*dw1);
    if (lane == 0) g_align[row] = sd;
}

// ---------------------------------------------------------------------------
// Kernel 2: 128x128 fp8 tile Gram (fp16 acc), 256 threads, 2 CTAs/SM,
// double-buffered K-halves, diag tiles alias B=A. Smem 64 KB/CTA.
// Row pitch 128 B (8 chunks); swizzle chunk' = chunk ^ (row&7).
extern __shared__ char gsm[];
#define A_OFF(h) ((h) * 16384)
#define B_OFF(h) (32768 + (h) * 16384)
#define SMEM_TOTAL 65536

__global__ __launch_bounds__(256, 2) void gram_kernel() {
    const int tid  = threadIdx.x;
    const int wid  = tid >> 5;
    const int lane = tid & 31;
    const uint32_t smem_base = smem_u32(gsm);

    // tile -> (by, bx), by <= bx
    int by = 0, rem = blockIdx.x;
    while (rem >= NB - by) { rem -= NB - by; by++; }
    const int bx   = by + rem;
    const bool diag = (bx == by);

    const uint8_t* __restrict__ xa = g_x8 + (size_t)(by * TILE) * D;
    const uint8_t* __restrict__ xb = g_x8 + (size_t)(bx * TILE) * D;

    // ---- Prefetch both K-halves (commit group per half) ----
    #pragma unroll
    for (int h = 0; h < 2; h++) {
        #pragma unroll
        for (int t = 0; t < 4; t++) {          // A: 128 rows x 8 chunks
            int i = tid + t * 256;
            int r = i >> 3, c = i & 7;
            cp_async16(smem_base + A_OFF(h) + r * 128 + ((c ^ (r & 7)) << 4),
                       xa + (size_t)r * D + h * 128 + c * 16);
        }
        if (!diag) {
            #pragma unroll
            for (int t = 0; t < 4; t++) {      // B: 128 rows x 8 chunks
                int i = tid + t * 256;
                int r = i >> 3, c = i & 7;
                cp_async16(smem_base + B_OFF(h) + r * 128 + ((c ^ (r & 7)) << 4),
                           xb + (size_t)r * D + h * 128 + c * 16);
            }
        }
        CP_COMMIT();
    }

    // ---- Warp tiling: 4 (m) x 2 (n); warp tile 32 x 64 (same as champion) ----
    const int warp_m = wid >> 1;               // 0..3
    const int warp_n = wid & 1;                // 0..1

    uint32_t a_row[2], a_rx[2];
    #pragma unroll
    for (int mt = 0; mt < 2; mt++) {
        int r = warp_m * 32 + mt * 16 + (lane & 15);
        a_row[mt] = (uint32_t)r * 128;
        a_rx[mt]  = r & 7;
    }
    const uint32_t a_c0 = lane >> 4;

    uint32_t b_row[4], b_rx[4];
    #pragma unroll
    for (int nt2 = 0; nt2 < 4; nt2++) {
        int r = warp_n * 64 + nt2 * 16 + (lane >> 4) * 8 + (lane & 7);
        b_row[nt2] = (uint32_t)r * 128;
        b_rx[nt2]  = r & 7;
    }
    const uint32_t b_c0 = (lane >> 3) & 1;

    uint32_t acc[2][8][2];                     // fp16x2 accumulators
    #pragma unroll
    for (int mt = 0; mt < 2; mt++)
        #pragma unroll
        for (int nt = 0; nt < 8; nt++) { acc[mt][nt][0] = 0u; acc[mt][nt][1] = 0u; }

    #pragma unroll
    for (int h = 0; h < 2; h++) {
        if (h == 0) { CP_WAIT(1); } else { CP_WAIT(0); }
        __syncthreads();

        const uint32_t abase = smem_base + A_OFF(h);
        const uint32_t bbase = diag ? abase : (smem_base + B_OFF(h));

        #pragma unroll
        for (int ks = 0; ks < 4; ks++) {
            uint32_t af[2][4];
            #pragma unroll
            for (int mt = 0; mt < 2; mt++)
                ldmatrix_x4(af[mt][0], af[mt][1], af[mt][2], af[mt][3],
                            abase + a_row[mt] + (((2 * ks + a_c0) ^ a_rx[mt]) << 4));
            uint32_t bf[8][2];
            #pragma unroll
            for (int nt2 = 0; nt2 < 4; nt2++) {
                uint32_t r0, r1, r2, r3;
                ldmatrix_x4(r0, r1, r2, r3,
                            bbase + b_row[nt2] + (((2 * ks + b_c0) ^ b_rx[nt2]) << 4));
                bf[nt2 * 2 + 0][0] = r0; bf[nt2 * 2 + 0][1] = r1;
                bf[nt2 * 2 + 1][0] = r2; bf[nt2 * 2 + 1][1] = r3;
            }
            #pragma unroll
            for (int mt = 0; mt < 2; mt++)
                #pragma unroll
                for (int nt = 0; nt < 8; nt++)
                    mma_fp8_h(acc[mt][nt], af[mt], bf[nt]);
        }
        if (h == 0) __syncthreads();
    }

    // ---- Fused epilogue: e = exp(4*min(c-1,0)); include iff gcol > grow ----
    const int gid = lane >> 2;
    const int tig = lane & 3;
    const int grow0 = by * TILE + warp_m * 32 + gid;
    const int gcol0 = bx * TILE + warp_n * 64 + tig * 2;
    float s = 0.0f;
    #pragma unroll
    for (int mt = 0; mt < 2; mt++) {
        #pragma unroll
        for (int nt = 0; nt < 8; nt++) {
            float2 f0 = __half22float2(*(const __half2*)&acc[mt][nt][0]);
            float2 f1 = __half22float2(*(const __half2*)&acc[mt][nt][1]);
            const int gr = grow0 + mt * 16;
            const int gc = gcol0 + nt * 8;
            float e;
            e = __expf(4.0f * fminf(f0.x - 1.0f, 0.0f)); if (gc     > gr    ) s += e;
            e = __expf(4.0f * fminf(f0.y - 1.0f, 0.0f)); if (gc + 1 > gr    ) s += e;
            e = __expf(4.0f * fminf(f1.x - 1.0f, 0.0f)); if (gc     > gr + 8) s += e;
            e = __expf(4.0f * fminf(f1.y - 1.0f, 0.0f)); if (gc + 1 > gr + 8) s += e;
        }
    }

    s = block_reduce<8>(s);
    if (tid == 0) g_part[blockIdx.x] = s;
}

// ---------------------------------------------------------------------------
__global__ __launch_bounds__(256) void finalize_kernel(float* __restrict__ out) {
    float sa = 0.0f, su = 0.0f;
    for (int i = threadIdx.x; i < BROWS;  i += 256) sa += g_align[i];
    for (int i = threadIdx.x; i < NTILES; i += 256) su += g_part[i];
    sa = block_reduce<8>(sa);
    su = block_reduce<8>(su);
    if (threadIdx.x == 0) {
        double align_loss   = (double)sa / (double)BROWS;
        double uniform_loss = 2.0 * (double)su / ((double)NTOT * (double)(NTOT - 1));
        out[0] = (float)(align_loss + uniform_loss);
    }
}

// ---------------------------------------------------------------------------
extern "C" void kernel_launch(void* const* d_in, const int* in_sizes, int n_in,
                              void* d_out, int out_size) {
    const float* a = (const float*)d_in[0];
    const float* b = (const float*)d_in[1];
    float* out = (float*)d_out;

    cudaFuncSetAttribute(gram_kernel,
                         cudaFuncAttributeMaxDynamicSharedMemorySize, SMEM_TOTAL);

    normalize_kernel<<<BROWS / 8, 256>>>(a, b);
    gram_kernel<<<NTILES, 256, SMEM_TOTAL>>>();
    finalize_kernel<<<1, 256>>>(out);
}